// round 7
// baseline (speedup 1.0000x reference)
#include <cuda_runtime.h>

#define NNODES 50000
#define NEDGES 800000
#define FDIM 128

// ---------------- scratch (no allocation allowed) ----------------
__device__ int   g_is64;
__device__ int   g_cnt[NNODES];
__device__ float g_dinv[NNODES];
__device__ int   g_rowstart[NNODES + 1];
__device__ int   g_cursor[NNODES];
__device__ int   g_col[NEDGES];
__device__ float g_w[NEDGES];
__device__ float g_h[(size_t)NNODES * FDIM];   // GEMM output (both layers)
__device__ float g_y1[(size_t)NNODES * FDIM];  // layer-1 aggregated output

// ---------------- dtype detection ----------------
// If edge_index is int64 (little-endian, values < 50000), every odd int32
// word is 0. If it was downcast to int32, odd words are random node ids.
__global__ void k_detect(const int* __restrict__ ei32) {
    if (blockIdx.x == 0 && threadIdx.x == 0) {
        int is64 = 1;
        #pragma unroll 1
        for (int i = 0; i < 64; i++) {
            if (ei32[2 * i + 1] != 0) { is64 = 0; break; }
        }
        g_is64 = is64;
    }
}

__device__ __forceinline__ int load_idx(const void* ei, size_t pos) {
    if (g_is64) return (int)((const long long*)ei)[pos];
    return ((const int*)ei)[pos];
}

// ---------------- graph build ----------------
__global__ void k_init(int n) {
    int i = blockIdx.x * blockDim.x + threadIdx.x;
    if (i < n) g_cnt[i] = 0;
}

__global__ void k_count(const void* __restrict__ ei, int E) {
    int e = blockIdx.x * blockDim.x + threadIdx.x;
    if (e < E) {
        int d = load_idx(ei, (size_t)E + e);
        atomicAdd(&g_cnt[d], 1);
    }
}

__global__ void k_dinv(int n) {
    int i = blockIdx.x * blockDim.x + threadIdx.x;
    if (i < n) g_dinv[i] = rsqrtf((float)(g_cnt[i] + 1));  // +1 self-loop
}

// single-block exclusive scan over g_cnt -> g_rowstart / g_cursor
__global__ void k_scan(int n, int E) {
    __shared__ int sh[1024];
    __shared__ int s_carry;
    int tid = threadIdx.x;
    if (tid == 0) s_carry = 0;
    __syncthreads();
    for (int base = 0; base < n; base += 1024) {
        int i = base + tid;
        int v = (i < n) ? g_cnt[i] : 0;
        sh[tid] = v;
        __syncthreads();
        #pragma unroll
        for (int off = 1; off < 1024; off <<= 1) {
            int t = (tid >= off) ? sh[tid - off] : 0;
            __syncthreads();
            sh[tid] += t;
            __syncthreads();
        }
        int excl = sh[tid] - v + s_carry;
        if (i < n) { g_rowstart[i] = excl; g_cursor[i] = excl; }
        int total = sh[1023];
        __syncthreads();
        if (tid == 0) s_carry += total;
        __syncthreads();
    }
    if (tid == 0) g_rowstart[n] = s_carry;  // == E
}

__global__ void k_scatter(const void* __restrict__ ei, int E) {
    int e = blockIdx.x * blockDim.x + threadIdx.x;
    if (e < E) {
        int s = load_idx(ei, e);
        int d = load_idx(ei, (size_t)E + e);
        int p = atomicAdd(&g_cursor[d], 1);
        g_col[p] = s;
        g_w[p]   = g_dinv[s];   // dinv[dst] applied in epilogue
    }
}

// ---------------- GEMM: C[M,128] = A[M,128] @ W[128,128] (fp32) ----------------
// 128x128 block tile, 256 threads, 8x8 per thread, K chunked by 32.
// Static shared only (~33 KB) -> no cudaFuncSetAttribute needed.
__device__ __forceinline__ void gemm_impl(const float* __restrict__ A,
                                          const float* __restrict__ W,
                                          float* __restrict__ C, int M) {
    __shared__ float As[128][33];   // K-chunk 32, pad to 33
    __shared__ float Bs[32][128];

    int tid = threadIdx.x;
    int m0  = blockIdx.x * 128;

    int tm = (tid >> 4) * 8;   // row offset within tile
    int tn = (tid & 15) * 8;   // col offset within tile

    float acc[8][8];
    #pragma unroll
    for (int i = 0; i < 8; i++)
        #pragma unroll
        for (int j = 0; j < 8; j++) acc[i][j] = 0.f;

    const float4* A4 = (const float4*)A;
    const float4* W4 = (const float4*)W;

    #pragma unroll
    for (int kc = 0; kc < 4; kc++) {
        // load A chunk: 128 rows x 32 cols = 1024 float4 (4 per thread)
        #pragma unroll
        for (int l = 0; l < 4; l++) {
            int idx = l * 256 + tid;
            int m   = idx >> 3;          // 0..127
            int k4  = idx & 7;           // 0..7 (float4 within 32-col chunk)
            float4 v = make_float4(0.f, 0.f, 0.f, 0.f);
            if (m0 + m < M) v = A4[(size_t)(m0 + m) * 32 + kc * 8 + k4];
            As[m][k4 * 4 + 0] = v.x;
            As[m][k4 * 4 + 1] = v.y;
            As[m][k4 * 4 + 2] = v.z;
            As[m][k4 * 4 + 3] = v.w;
        }
        // load B chunk: 32 rows x 128 cols = 1024 float4 (4 per thread)
        #pragma unroll
        for (int l = 0; l < 4; l++) {
            int idx = l * 256 + tid;
            int r   = idx >> 5;          // 0..31
            int c4  = idx & 31;          // 0..31
            float4 v = W4[(size_t)(kc * 32 + r) * 32 + c4];
            *(float4*)&Bs[r][c4 * 4] = v;
        }
        __syncthreads();

        #pragma unroll
        for (int k = 0; k < 32; k++) {
            float a[8];
            #pragma unroll
            for (int i = 0; i < 8; i++) a[i] = As[tm + i][k];
            float4 b0 = *(const float4*)&Bs[k][tn];
            float4 b1 = *(const float4*)&Bs[k][tn + 4];
            float b[8] = {b0.x, b0.y, b0.z, b0.w, b1.x, b1.y, b1.z, b1.w};
            #pragma unroll
            for (int i = 0; i < 8; i++)
                #pragma unroll
                for (int j = 0; j < 8; j++)
                    acc[i][j] += a[i] * b[j];
        }
        __syncthreads();
    }

    #pragma unroll
    for (int i = 0; i < 8; i++) {
        int m = m0 + tm + i;
        if (m < M) {
            float4* Crow = (float4*)&C[(size_t)m * 128 + tn];
            Crow[0] = make_float4(acc[i][0], acc[i][1], acc[i][2], acc[i][3]);
            Crow[1] = make_float4(acc[i][4], acc[i][5], acc[i][6], acc[i][7]);
        }
    }
}

__global__ void k_gemm1(const float* __restrict__ x, const float* __restrict__ W, int M) {
    gemm_impl(x, W, g_h, M);
}
__global__ void k_gemm2(const float* __restrict__ W, int M) {
    gemm_impl(g_y1, W, g_h, M);
}

// ---------------- aggregation: warp per node ----------------
// out[d] = relu( dinv[d]*sum_e dinv[src_e]*h[src_e] + dinv[d]^2*h[d] + b )
__device__ __forceinline__ void agg_impl(const float* __restrict__ h,
                                         const float* __restrict__ bias,
                                         float* __restrict__ out, int N) {
    int gwarp = (blockIdx.x * blockDim.x + threadIdx.x) >> 5;
    if (gwarp >= N) return;
    int lane = threadIdx.x & 31;

    int s = g_rowstart[gwarp];
    int e = g_rowstart[gwarp + 1];

    const float4* h4 = (const float4*)h;
    float4 acc = make_float4(0.f, 0.f, 0.f, 0.f);

    for (int i = s; i < e; i += 32) {
        int j = i + lane;
        int   srcv = (j < e) ? __ldg(&g_col[j]) : 0;
        float wv   = (j < e) ? __ldg(&g_w[j])   : 0.f;
        int nb = min(32, e - i);
        for (int t = 0; t < nb; t++) {
            int   sv = __shfl_sync(0xffffffffu, srcv, t);
            float ww = __shfl_sync(0xffffffffu, wv, t);
            float4 v = h4[(size_t)sv * 32 + lane];
            acc.x += v.x * ww; acc.y += v.y * ww;
            acc.z += v.z * ww; acc.w += v.w * ww;
        }
    }

    float di  = g_dinv[gwarp];
    float di2 = di * di;
    float4 sv = h4[(size_t)gwarp * 32 + lane];
    float4 bv = ((const float4*)bias)[lane];

    float4 o;
    o.x = fmaxf(di * acc.x + di2 * sv.x + bv.x, 0.f);
    o.y = fmaxf(di * acc.y + di2 * sv.y + bv.y, 0.f);
    o.z = fmaxf(di * acc.z + di2 * sv.z + bv.z, 0.f);
    o.w = fmaxf(di * acc.w + di2 * sv.w + bv.w, 0.f);
    ((float4*)out)[(size_t)gwarp * 32 + lane] = o;
}

__global__ void k_agg1(const float* __restrict__ bias, int N) {
    agg_impl(g_h, bias, g_y1, N);
}
__global__ void k_agg2(const float* __restrict__ bias, float* __restrict__ out, int N) {
    agg_impl(g_h, bias, out, N);
}

// ---------------- launch ----------------
extern "C" void kernel_launch(void* const* d_in, const int* in_sizes, int n_in,
                              void* d_out, int out_size) {
    const float* x  = (const float*)d_in[0];
    const void*  ei = d_in[1];
    const float* W1 = (const float*)d_in[2];
    const float* b1 = (const float*)d_in[3];
    const float* W2 = (const float*)d_in[4];
    const float* b2 = (const float*)d_in[5];
    float* out = (float*)d_out;

    int N = in_sizes[0] / FDIM;
    int E = in_sizes[1] / 2;

    // dtype probe + graph build (shared by both layers)
    k_detect <<<1, 32>>>((const int*)ei);
    k_init   <<<(N + 255) / 256, 256>>>(N);
    k_count  <<<(E + 255) / 256, 256>>>(ei, E);
    k_dinv   <<<(N + 255) / 256, 256>>>(N);
    k_scan   <<<1, 1024>>>(N, E);
    k_scatter<<<(E + 255) / 256, 256>>>(ei, E);

    int gemm_blocks = (N + 127) / 128;
    int agg_blocks  = (int)(((size_t)N * 32 + 255) / 256);

    // layer 1
    k_gemm1<<<gemm_blocks, 256>>>(x, W1, N);
    k_agg1 <<<agg_blocks, 256>>>(b1, N);
    // layer 2
    k_gemm2<<<gemm_blocks, 256>>>(W2, N);
    k_agg2 <<<agg_blocks, 256>>>(b2, out, N);
}

// round 8
// speedup vs baseline: 2.1687x; 2.1687x over previous
#include <cuda_runtime.h>

#define NNODES 50000
#define NEDGES 800000
#define FDIM 128

// ---------------- scratch (no allocation allowed) ----------------
__device__ int   g_is64;
__device__ int   g_cnt[NNODES];
__device__ float g_dinv[NNODES];
__device__ int   g_rowstart[NNODES + 1];
__device__ int   g_cursor[NNODES];
__device__ int   g_col[NEDGES];
__device__ float g_w[NEDGES];
__device__ float g_h[(size_t)NNODES * FDIM];   // GEMM output (both layers)
__device__ float g_y1[(size_t)NNODES * FDIM];  // layer-1 aggregated output

// ---------------- helpers ----------------
__device__ __forceinline__ int load_idx(const void* ei, size_t pos) {
    if (g_is64) return (int)((const long long*)ei)[pos];
    return ((const int*)ei)[pos];
}

__device__ __forceinline__ float f2tf(float f) {
    unsigned r;
    asm("cvt.rna.tf32.f32 %0, %1;" : "=r"(r) : "f"(f));
    return __uint_as_float(r);
}

__device__ __forceinline__ void mma_tf32(float* c, const unsigned* a, const unsigned* b) {
    asm volatile(
        "mma.sync.aligned.m16n8k8.row.col.f32.tf32.tf32.f32 "
        "{%0,%1,%2,%3}, {%4,%5,%6,%7}, {%8,%9}, {%0,%1,%2,%3};"
        : "+f"(c[0]), "+f"(c[1]), "+f"(c[2]), "+f"(c[3])
        : "r"(a[0]), "r"(a[1]), "r"(a[2]), "r"(a[3]), "r"(b[0]), "r"(b[1]));
}

// ---------------- graph build ----------------
// init counts + (thread 0) edge dtype detection.
// int64 little-endian with values < 2^31 => every odd int32 word is 0.
__global__ void k_pre(const int* __restrict__ ei32, int n) {
    int i = blockIdx.x * blockDim.x + threadIdx.x;
    if (i < n) g_cnt[i] = 0;
    if (i == 0) {
        int is64 = 1;
        #pragma unroll 1
        for (int t = 0; t < 64; t++)
            if (ei32[2 * t + 1] != 0) { is64 = 0; break; }
        g_is64 = is64;
    }
}

__global__ void k_count(const void* __restrict__ ei, int E) {
    int e = blockIdx.x * blockDim.x + threadIdx.x;
    if (e < E) {
        int d = load_idx(ei, (size_t)E + e);
        atomicAdd(&g_cnt[d], 1);
    }
}

// single-block shuffle scan over g_cnt -> rowstart/cursor; also dinv.
__global__ void k_scan(int n) {
    __shared__ int warp_off[32];
    __shared__ int s_carry;
    int tid = threadIdx.x, lane = tid & 31, wid = tid >> 5;
    if (tid == 0) s_carry = 0;
    __syncthreads();
    for (int base = 0; base < n; base += 1024) {
        int i = base + tid;
        int v = (i < n) ? g_cnt[i] : 0;
        int incl = v;
        #pragma unroll
        for (int off = 1; off < 32; off <<= 1) {
            int t = __shfl_up_sync(0xffffffffu, incl, off);
            if (lane >= off) incl += t;
        }
        if (lane == 31) warp_off[wid] = incl;
        __syncthreads();
        if (wid == 0) {
            int wv = warp_off[lane];
            int wincl = wv;
            #pragma unroll
            for (int off = 1; off < 32; off <<= 1) {
                int t = __shfl_up_sync(0xffffffffu, wincl, off);
                if (lane >= off) wincl += t;
            }
            warp_off[lane] = wincl - wv;  // exclusive warp offset
        }
        __syncthreads();
        int excl = s_carry + warp_off[wid] + incl - v;
        if (i < n) {
            g_rowstart[i] = excl;
            g_cursor[i]   = excl;
            g_dinv[i]     = rsqrtf((float)(v + 1));  // +1 self-loop
        }
        __syncthreads();
        if (tid == 1023) s_carry = excl + v;  // running total
        __syncthreads();
    }
    if (tid == 0) g_rowstart[n] = s_carry;  // == E
}

__global__ void k_scatter(const void* __restrict__ ei, int E) {
    int e = blockIdx.x * blockDim.x + threadIdx.x;
    if (e < E) {
        int s = load_idx(ei, e);
        int d = load_idx(ei, (size_t)E + e);
        int p = atomicAdd(&g_cursor[d], 1);
        g_col[p] = s;
        g_w[p]   = g_dinv[s];   // dinv[dst] applied in epilogue
    }
}

// ---------------- GEMM: C[M,128] = A[M,128] @ W[128,128] via tf32 mma.sync ---
// 128x128 block tile, 8 warps. Warp tile 32x64 (2 m-tiles x 8 n-tiles of
// m16n8k8). K chunked by 32. tf32 conversion done at the smem-fill stage.
// Padding: As stride 36 (bank = 4*g+t), Bs stride 136 (bank = 8*t+g):
// every fragment LDS is conflict-free.
__device__ __forceinline__ void gemm_impl(const float* __restrict__ A,
                                          const float* __restrict__ W,
                                          float* __restrict__ C, int M) {
    __shared__ float As[128][36];
    __shared__ float Bs[32][136];

    int tid  = threadIdx.x;
    int m0   = blockIdx.x * 128;
    int wid  = tid >> 5, lane = tid & 31;
    int warp_m = wid & 3;        // 0..3 -> 32-row slice
    int warp_n = wid >> 2;       // 0..1 -> 64-col slice
    int gID  = lane >> 2;        // 0..7
    int tig  = lane & 3;         // 0..3

    float acc[2][8][4];
    #pragma unroll
    for (int mt = 0; mt < 2; mt++)
        #pragma unroll
        for (int nt = 0; nt < 8; nt++)
            #pragma unroll
            for (int r = 0; r < 4; r++) acc[mt][nt][r] = 0.f;

    const float4* A4 = (const float4*)A;
    const float4* W4 = (const float4*)W;

    #pragma unroll
    for (int kc = 0; kc < 4; kc++) {
        // fill A chunk: 128 x 32 (tf32-rounded)
        #pragma unroll
        for (int l = 0; l < 4; l++) {
            int idx = l * 256 + tid;
            int m   = idx >> 3;      // 0..127
            int k4  = idx & 7;       // 0..7
            float4 v = make_float4(0.f, 0.f, 0.f, 0.f);
            if (m0 + m < M) v = A4[(size_t)(m0 + m) * 32 + kc * 8 + k4];
            As[m][k4 * 4 + 0] = f2tf(v.x);
            As[m][k4 * 4 + 1] = f2tf(v.y);
            As[m][k4 * 4 + 2] = f2tf(v.z);
            As[m][k4 * 4 + 3] = f2tf(v.w);
        }
        // fill B chunk: 32 x 128 (tf32-rounded)
        #pragma unroll
        for (int l = 0; l < 4; l++) {
            int idx = l * 256 + tid;
            int r   = idx >> 5;      // 0..31
            int c4  = idx & 31;      // 0..31
            float4 v = W4[(size_t)(kc * 32 + r) * 32 + c4];
            Bs[r][c4 * 4 + 0] = f2tf(v.x);
            Bs[r][c4 * 4 + 1] = f2tf(v.y);
            Bs[r][c4 * 4 + 2] = f2tf(v.z);
            Bs[r][c4 * 4 + 3] = f2tf(v.w);
        }
        __syncthreads();

        #pragma unroll
        for (int kk = 0; kk < 4; kk++) {
            int cb = kk * 8;
            unsigned a[2][4];
            #pragma unroll
            for (int mt = 0; mt < 2; mt++) {
                int rb = warp_m * 32 + mt * 16;
                a[mt][0] = __float_as_uint(As[rb + gID    ][cb + tig    ]);
                a[mt][1] = __float_as_uint(As[rb + gID + 8][cb + tig    ]);
                a[mt][2] = __float_as_uint(As[rb + gID    ][cb + tig + 4]);
                a[mt][3] = __float_as_uint(As[rb + gID + 8][cb + tig + 4]);
            }
            unsigned b[8][2];
            #pragma unroll
            for (int nt = 0; nt < 8; nt++) {
                int nb = warp_n * 64 + nt * 8;
                b[nt][0] = __float_as_uint(Bs[cb + tig    ][nb + gID]);
                b[nt][1] = __float_as_uint(Bs[cb + tig + 4][nb + gID]);
            }
            #pragma unroll
            for (int mt = 0; mt < 2; mt++)
                #pragma unroll
                for (int nt = 0; nt < 8; nt++)
                    mma_tf32(acc[mt][nt], a[mt], b[nt]);
        }
        __syncthreads();
    }

    // epilogue: c0/c1 -> (row, 2t), (row, 2t+1); c2/c3 -> row+8
    #pragma unroll
    for (int mt = 0; mt < 2; mt++) {
        int row0 = m0 + warp_m * 32 + mt * 16 + gID;
        #pragma unroll
        for (int nt = 0; nt < 8; nt++) {
            int col = warp_n * 64 + nt * 8 + tig * 2;
            if (row0 < M)
                *(float2*)&C[(size_t)row0 * 128 + col] =
                    make_float2(acc[mt][nt][0], acc[mt][nt][1]);
            if (row0 + 8 < M)
                *(float2*)&C[(size_t)(row0 + 8) * 128 + col] =
                    make_float2(acc[mt][nt][2], acc[mt][nt][3]);
        }
    }
}

__global__ void __launch_bounds__(256, 2)
k_gemm1(const float* __restrict__ x, const float* __restrict__ W, int M) {
    gemm_impl(x, W, g_h, M);
}
__global__ void __launch_bounds__(256, 2)
k_gemm2(const float* __restrict__ W, int M) {
    gemm_impl(g_y1, W, g_h, M);
}

// ---------------- aggregation: warp per node ----------------
// out[d] = relu( dinv[d]*sum_e dinv[src_e]*h[src_e] + dinv[d]^2*h[d] + b )
__device__ __forceinline__ void agg_impl(const float* __restrict__ h,
                                         const float* __restrict__ bias,
                                         float* __restrict__ out, int N) {
    int gwarp = (blockIdx.x * blockDim.x + threadIdx.x) >> 5;
    if (gwarp >= N) return;
    int lane = threadIdx.x & 31;

    int s = g_rowstart[gwarp];
    int e = g_rowstart[gwarp + 1];

    const float4* h4 = (const float4*)h;
    float4 acc = make_float4(0.f, 0.f, 0.f, 0.f);

    for (int i = s; i < e; i += 32) {
        int j = i + lane;
        int   srcv = (j < e) ? __ldg(&g_col[j]) : 0;
        float wv   = (j < e) ? __ldg(&g_w[j])   : 0.f;
        int nb = min(32, e - i);
        for (int t = 0; t < nb; t++) {
            int   sv = __shfl_sync(0xffffffffu, srcv, t);
            float ww = __shfl_sync(0xffffffffu, wv, t);
            float4 v = h4[(size_t)sv * 32 + lane];
            acc.x += v.x * ww; acc.y += v.y * ww;
            acc.z += v.z * ww; acc.w += v.w * ww;
        }
    }

    float di  = g_dinv[gwarp];
    float di2 = di * di;
    float4 sv = h4[(size_t)gwarp * 32 + lane];
    float4 bv = ((const float4*)bias)[lane];

    float4 o;
    o.x = fmaxf(di * acc.x + di2 * sv.x + bv.x, 0.f);
    o.y = fmaxf(di * acc.y + di2 * sv.y + bv.y, 0.f);
    o.z = fmaxf(di * acc.z + di2 * sv.z + bv.z, 0.f);
    o.w = fmaxf(di * acc.w + di2 * sv.w + bv.w, 0.f);
    ((float4*)out)[(size_t)gwarp * 32 + lane] = o;
}

__global__ void k_agg1(const float* __restrict__ bias, int N) {
    agg_impl(g_h, bias, g_y1, N);
}
__global__ void k_agg2(const float* __restrict__ bias, float* __restrict__ out, int N) {
    agg_impl(g_h, bias, out, N);
}

// ---------------- launch ----------------
extern "C" void kernel_launch(void* const* d_in, const int* in_sizes, int n_in,
                              void* d_out, int out_size) {
    const float* x  = (const float*)d_in[0];
    const void*  ei = d_in[1];
    const float* W1 = (const float*)d_in[2];
    const float* b1 = (const float*)d_in[3];
    const float* W2 = (const float*)d_in[4];
    const float* b2 = (const float*)d_in[5];
    float* out = (float*)d_out;

    int N = in_sizes[0] / FDIM;
    int E = in_sizes[1] / 2;

    // graph build (shared by both layers)
    k_pre    <<<(N + 255) / 256, 256>>>((const int*)ei, N);
    k_count  <<<(E + 255) / 256, 256>>>(ei, E);
    k_scan   <<<1, 1024>>>(N);
    k_scatter<<<(E + 255) / 256, 256>>>(ei, E);

    int gemm_blocks = (N + 127) / 128;
    int agg_blocks  = (int)(((size_t)N * 32 + 255) / 256);

    // layer 1
    k_gemm1<<<gemm_blocks, 256>>>(x, W1, N);
    k_agg1 <<<agg_blocks, 256>>>(b1, N);
    // layer 2
    k_gemm2<<<gemm_blocks, 256>>>(W2, N);
    k_agg2 <<<agg_blocks, 256>>>(b2, out, N);
}

// round 11
// speedup vs baseline: 2.4857x; 1.1462x over previous
#include <cuda_runtime.h>

#define NNODES 50000
#define NEDGES 800000
#define FDIM 128

// ---------------- scratch (no allocation allowed) ----------------
__device__ int   g_is64;
__device__ int   g_alloc;
__device__ int   g_cnt[NNODES];
__device__ float g_dinv[NNODES];
__device__ int   g_rowstart[NNODES];
__device__ int   g_cursor[NNODES];
__device__ int   g_col[NEDGES];
__device__ float g_w[NEDGES];
__device__ float g_h[(size_t)NNODES * FDIM];   // GEMM output (both layers)
__device__ float g_y1[(size_t)NNODES * FDIM];  // layer-1 aggregated output

// ---------------- helpers ----------------
__device__ __forceinline__ int load_idx(const void* ei, size_t pos) {
    if (g_is64) return (int)((const long long*)ei)[pos];
    return ((const int*)ei)[pos];
}

__device__ __forceinline__ float f2tf(float f) {
    unsigned r;
    asm("cvt.rna.tf32.f32 %0, %1;" : "=r"(r) : "f"(f));
    return __uint_as_float(r);
}

__device__ __forceinline__ void mma_tf32(float* c, const unsigned* a, const unsigned* b) {
    asm volatile(
        "mma.sync.aligned.m16n8k8.row.col.f32.tf32.tf32.f32 "
        "{%0,%1,%2,%3}, {%4,%5,%6,%7}, {%8,%9}, {%0,%1,%2,%3};"
        : "+f"(c[0]), "+f"(c[1]), "+f"(c[2]), "+f"(c[3])
        : "r"(a[0]), "r"(a[1]), "r"(a[2]), "r"(a[3]), "r"(b[0]), "r"(b[1]));
}

// ---------------- graph build ----------------
// init counts + alloc counter + (thread 0) edge dtype detection.
__global__ void k_pre(const int* __restrict__ ei32, int n) {
    int i = blockIdx.x * blockDim.x + threadIdx.x;
    if (i < n) g_cnt[i] = 0;
    if (i == 0) {
        g_alloc = 0;
        int is64 = 1;
        #pragma unroll 1
        for (int t = 0; t < 64; t++)
            if (ei32[2 * t + 1] != 0) { is64 = 0; break; }
        g_is64 = is64;
    }
}

// 4 edges per thread, grid-stride spacing (coalesced, 4 REDs in flight)
__global__ void k_count(const void* __restrict__ ei, int E, int S) {
    int t0 = blockIdx.x * blockDim.x + threadIdx.x;
    #pragma unroll
    for (int j = 0; j < 4; j++) {
        int e = t0 + j * S;
        if (e < E) {
            int d = load_idx(ei, (size_t)E + e);
            atomicAdd(&g_cnt[d], 1);
        }
    }
}

// unordered CSR row allocation: warp-aggregated atomic on g_alloc.
// Also computes dinv. Replaces the serial scan.
__global__ void k_assign(int n) {
    int i = blockIdx.x * blockDim.x + threadIdx.x;
    int lane = threadIdx.x & 31;
    int c = (i < n) ? g_cnt[i] : 0;
    // warp inclusive scan
    int incl = c;
    #pragma unroll
    for (int off = 1; off < 32; off <<= 1) {
        int t = __shfl_up_sync(0xffffffffu, incl, off);
        if (lane >= off) incl += t;
    }
    int total = __shfl_sync(0xffffffffu, incl, 31);
    int base = 0;
    if (lane == 0) base = atomicAdd(&g_alloc, total);
    base = __shfl_sync(0xffffffffu, base, 0);
    if (i < n) {
        int off = base + incl - c;
        g_rowstart[i] = off;
        g_cursor[i]   = off;
        g_dinv[i]     = rsqrtf((float)(c + 1));  // +1 self-loop
    }
}

__global__ void k_scatter(const void* __restrict__ ei, int E, int S) {
    int t0 = blockIdx.x * blockDim.x + threadIdx.x;
    #pragma unroll
    for (int j = 0; j < 4; j++) {
        int e = t0 + j * S;
        if (e < E) {
            int s = load_idx(ei, e);
            int d = load_idx(ei, (size_t)E + e);
            int p = atomicAdd(&g_cursor[d], 1);
            g_col[p] = s;
            g_w[p]   = g_dinv[s];   // dinv[dst] applied in epilogue
        }
    }
}

// ---------------- GEMM: C[M,128] = A[M,128] @ W[128,128] via tf32 mma.sync ---
// 128x128 block tile, 8 warps, warp tile 32x64 (2 m x 8 n of m16n8k8).
// K chunked by 32 with REGISTER PREFETCH: next chunk's LDGs are issued right
// after the smem stores, overlapping GMEM latency with the mma phase.
// Padding: As stride 36 (bank = 4*g+t), Bs stride 136 (bank = 8*t+g):
// every fragment LDS is conflict-free.
__device__ __forceinline__ void gemm_impl(const float* __restrict__ A,
                                          const float* __restrict__ W,
                                          float* __restrict__ C, int M) {
    __shared__ float As[128][36];
    __shared__ float Bs[32][136];

    int tid  = threadIdx.x;
    int m0   = blockIdx.x * 128;
    int wid  = tid >> 5, lane = tid & 31;
    int warp_m = wid & 3;        // 0..3 -> 32-row slice
    int warp_n = wid >> 2;       // 0..1 -> 64-col slice
    int gID  = lane >> 2;        // 0..7
    int tig  = lane & 3;         // 0..3

    // per-thread fill coordinates (constant across chunks)
    int am[4], ak4[4], br[4], bc4[4];
    bool aok[4];
    #pragma unroll
    for (int l = 0; l < 4; l++) {
        int idx = l * 256 + tid;
        am[l]  = idx >> 3;  ak4[l] = idx & 7;
        br[l]  = idx >> 5;  bc4[l] = idx & 31;
        aok[l] = (m0 + am[l]) < M;
    }

    const float4* A4 = (const float4*)A;
    const float4* W4 = (const float4*)W;

    float acc[2][8][4];
    #pragma unroll
    for (int mt = 0; mt < 2; mt++)
        #pragma unroll
        for (int nt = 0; nt < 8; nt++)
            #pragma unroll
            for (int r = 0; r < 4; r++) acc[mt][nt][r] = 0.f;

    float4 pa[4], pb[4];
    // prefetch chunk 0
    #pragma unroll
    for (int l = 0; l < 4; l++) {
        pa[l] = aok[l] ? A4[(size_t)(m0 + am[l]) * 32 + ak4[l]]
                       : make_float4(0.f, 0.f, 0.f, 0.f);
        pb[l] = W4[(size_t)br[l] * 32 + bc4[l]];
    }

    #pragma unroll
    for (int kc = 0; kc < 4; kc++) {
        // store current chunk (tf32-rounded)
        #pragma unroll
        for (int l = 0; l < 4; l++) {
            float4 va = make_float4(f2tf(pa[l].x), f2tf(pa[l].y),
                                    f2tf(pa[l].z), f2tf(pa[l].w));
            *(float4*)&As[am[l]][ak4[l] * 4] = va;
            float4 vb = make_float4(f2tf(pb[l].x), f2tf(pb[l].y),
                                    f2tf(pb[l].z), f2tf(pb[l].w));
            *(float4*)&Bs[br[l]][bc4[l] * 4] = vb;
        }
        // issue next chunk's loads before the barrier (overlap with mma)
        if (kc < 3) {
            #pragma unroll
            for (int l = 0; l < 4; l++) {
                pa[l] = aok[l] ? A4[(size_t)(m0 + am[l]) * 32 + (kc + 1) * 8 + ak4[l]]
                               : make_float4(0.f, 0.f, 0.f, 0.f);
                pb[l] = W4[(size_t)((kc + 1) * 32 + br[l]) * 32 + bc4[l]];
            }
        }
        __syncthreads();

        #pragma unroll
        for (int kk = 0; kk < 4; kk++) {
            int cb = kk * 8;
            unsigned a[2][4];
            #pragma unroll
            for (int mt = 0; mt < 2; mt++) {
                int rb = warp_m * 32 + mt * 16;
                a[mt][0] = __float_as_uint(As[rb + gID    ][cb + tig    ]);
                a[mt][1] = __float_as_uint(As[rb + gID + 8][cb + tig    ]);
                a[mt][2] = __float_as_uint(As[rb + gID    ][cb + tig + 4]);
                a[mt][3] = __float_as_uint(As[rb + gID + 8][cb + tig + 4]);
            }
            unsigned b[8][2];
            #pragma unroll
            for (int nt = 0; nt < 8; nt++) {
                int nb = warp_n * 64 + nt * 8;
                b[nt][0] = __float_as_uint(Bs[cb + tig    ][nb + gID]);
                b[nt][1] = __float_as_uint(Bs[cb + tig + 4][nb + gID]);
            }
            #pragma unroll
            for (int mt = 0; mt < 2; mt++)
                #pragma unroll
                for (int nt = 0; nt < 8; nt++)
                    mma_tf32(acc[mt][nt], a[mt], b[nt]);
        }
        __syncthreads();
    }

    // epilogue
    #pragma unroll
    for (int mt = 0; mt < 2; mt++) {
        int row0 = m0 + warp_m * 32 + mt * 16 + gID;
        #pragma unroll
        for (int nt = 0; nt < 8; nt++) {
            int col = warp_n * 64 + nt * 8 + tig * 2;
            if (row0 < M)
                *(float2*)&C[(size_t)row0 * 128 + col] =
                    make_float2(acc[mt][nt][0], acc[mt][nt][1]);
            if (row0 + 8 < M)
                *(float2*)&C[(size_t)(row0 + 8) * 128 + col] =
                    make_float2(acc[mt][nt][2], acc[mt][nt][3]);
        }
    }
}

__global__ void __launch_bounds__(256, 2)
k_gemm1(const float* __restrict__ x, const float* __restrict__ W, int M) {
    gemm_impl(x, W, g_h, M);
}
__global__ void __launch_bounds__(256, 2)
k_gemm2(const float* __restrict__ W, int M) {
    gemm_impl(g_y1, W, g_h, M);
}

// ---------------- aggregation: warp per node ----------------
// out[d] = relu( dinv[d]*sum_e dinv[src_e]*h[src_e] + dinv[d]^2*h[d] + b )
__device__ __forceinline__ void agg_impl(const float* __restrict__ h,
                                         const float* __restrict__ bias,
                                         float* __restrict__ out, int N) {
    int gwarp = (blockIdx.x * blockDim.x + threadIdx.x) >> 5;
    if (gwarp >= N) return;
    int lane = threadIdx.x & 31;

    int s = g_rowstart[gwarp];
    int e = s + g_cnt[gwarp];

    const float4* h4 = (const float4*)h;
    float4 acc = make_float4(0.f, 0.f, 0.f, 0.f);

    for (int i = s; i < e; i += 32) {
        int j = i + lane;
        int   srcv = (j < e) ? __ldg(&g_col[j]) : 0;
        float wv   = (j < e) ? __ldg(&g_w[j])   : 0.f;
        int nb = min(32, e - i);
        int t = 0;
        // unrolled-by-4 body: 4 independent gathers in flight
        for (; t + 4 <= nb; t += 4) {
            int   s0 = __shfl_sync(0xffffffffu, srcv, t);
            int   s1 = __shfl_sync(0xffffffffu, srcv, t + 1);
            int   s2 = __shfl_sync(0xffffffffu, srcv, t + 2);
            int   s3 = __shfl_sync(0xffffffffu, srcv, t + 3);
            float w0 = __shfl_sync(0xffffffffu, wv, t);
            float w1 = __shfl_sync(0xffffffffu, wv, t + 1);
            float w2 = __shfl_sync(0xffffffffu, wv, t + 2);
            float w3 = __shfl_sync(0xffffffffu, wv, t + 3);
            float4 v0 = h4[(size_t)s0 * 32 + lane];
            float4 v1 = h4[(size_t)s1 * 32 + lane];
            float4 v2 = h4[(size_t)s2 * 32 + lane];
            float4 v3 = h4[(size_t)s3 * 32 + lane];
            acc.x += v0.x * w0; acc.y += v0.y * w0; acc.z += v0.z * w0; acc.w += v0.w * w0;
            acc.x += v1.x * w1; acc.y += v1.y * w1; acc.z += v1.z * w1; acc.w += v1.w * w1;
            acc.x += v2.x * w2; acc.y += v2.y * w2; acc.z += v2.z * w2; acc.w += v2.w * w2;
            acc.x += v3.x * w3; acc.y += v3.y * w3; acc.z += v3.z * w3; acc.w += v3.w * w3;
        }
        for (; t < nb; t++) {
            int   sv = __shfl_sync(0xffffffffu, srcv, t);
            float ww = __shfl_sync(0xffffffffu, wv, t);
            float4 v = h4[(size_t)sv * 32 + lane];
            acc.x += v.x * ww; acc.y += v.y * ww;
            acc.z += v.z * ww; acc.w += v.w * ww;
        }
    }

    float di  = g_dinv[gwarp];
    float di2 = di * di;
    float4 sv = h4[(size_t)gwarp * 32 + lane];
    float4 bv = ((const float4*)bias)[lane];

    float4 o;
    o.x = fmaxf(di * acc.x + di2 * sv.x + bv.x, 0.f);
    o.y = fmaxf(di * acc.y + di2 * sv.y + bv.y, 0.f);
    o.z = fmaxf(di * acc.z + di2 * sv.z + bv.z, 0.f);
    o.w = fmaxf(di * acc.w + di2 * sv.w + bv.w, 0.f);
    ((float4*)out)[(size_t)gwarp * 32 + lane] = o;
}

__global__ void k_agg1(const float* __restrict__ bias, int N) {
    agg_impl(g_h, bias, g_y1, N);
}
__global__ void k_agg2(const float* __restrict__ bias, float* __restrict__ out, int N) {
    agg_impl(g_h, bias, out, N);
}

// ---------------- launch ----------------
extern "C" void kernel_launch(void* const* d_in, const int* in_sizes, int n_in,
                              void* d_out, int out_size) {
    const float* x  = (const float*)d_in[0];
    const void*  ei = d_in[1];
    const float* W1 = (const float*)d_in[2];
    const float* b1 = (const float*)d_in[3];
    const float* W2 = (const float*)d_in[4];
    const float* b2 = (const float*)d_in[5];
    float* out = (float*)d_out;

    int N = in_sizes[0] / FDIM;
    int E = in_sizes[1] / 2;

    int ethreads = (E + 3) / 4;                 // 4 edges per thread
    int eblocks  = (ethreads + 255) / 256;
    int S        = eblocks * 256;               // grid-stride spacing

    // graph build (shared by both layers)
    k_pre    <<<(N + 255) / 256, 256>>>((const int*)ei, N);
    k_count  <<<eblocks, 256>>>(ei, E, S);
    k_assign <<<(N + 255) / 256, 256>>>(N);
    k_scatter<<<eblocks, 256>>>(ei, E, S);

    int gemm_blocks = (N + 127) / 128;
    int agg_blocks  = (int)(((size_t)N * 32 + 255) / 256);

    // layer 1
    k_gemm1<<<gemm_blocks, 256>>>(x, W1, N);
    k_agg1 <<<agg_blocks, 256>>>(b1, N);
    // layer 2
    k_gemm2<<<gemm_blocks, 256>>>(W2, N);
    k_agg2 <<<agg_blocks, 256>>>(b2, out, N);
}

// round 12
// speedup vs baseline: 2.4929x; 1.0029x over previous
#include <cuda_runtime.h>
#include <cuda_fp16.h>

#define NNODES 50000
#define NEDGES 800000
#define FDIM 128

// ---------------- scratch (no allocation allowed) ----------------
__device__ int    g_is64;
__device__ int    g_alloc;
__device__ int    g_cnt[NNODES];
__device__ float  g_dinv[NNODES];
__device__ int    g_rowstart[NNODES];
__device__ int    g_cursor[NNODES];
__device__ int2   g_ew[NEDGES];                   // packed {src, w bits}
__device__ float  g_h[(size_t)NNODES * FDIM];     // GEMM output fp32 (self term)
__device__ __half g_hh[(size_t)NNODES * FDIM];    // GEMM output fp16 (gather path)
__device__ float  g_y1[(size_t)NNODES * FDIM];    // layer-1 aggregated output

// ---------------- helpers ----------------
__device__ __forceinline__ int load_idx(const void* ei, size_t pos) {
    if (g_is64) return (int)((const long long*)ei)[pos];
    return ((const int*)ei)[pos];
}

__device__ __forceinline__ float f2tf(float f) {
    unsigned r;
    asm("cvt.rna.tf32.f32 %0, %1;" : "=r"(r) : "f"(f));
    return __uint_as_float(r);
}

__device__ __forceinline__ void mma_tf32(float* c, const unsigned* a, const unsigned* b) {
    asm volatile(
        "mma.sync.aligned.m16n8k8.row.col.f32.tf32.tf32.f32 "
        "{%0,%1,%2,%3}, {%4,%5,%6,%7}, {%8,%9}, {%0,%1,%2,%3};"
        : "+f"(c[0]), "+f"(c[1]), "+f"(c[2]), "+f"(c[3])
        : "r"(a[0]), "r"(a[1]), "r"(a[2]), "r"(a[3]), "r"(b[0]), "r"(b[1]));
}

// ---------------- graph build ----------------
__global__ void k_pre(const int* __restrict__ ei32, int n) {
    int i = blockIdx.x * blockDim.x + threadIdx.x;
    if (i < n) g_cnt[i] = 0;
    if (i == 0) {
        g_alloc = 0;
        int is64 = 1;
        #pragma unroll 1
        for (int t = 0; t < 64; t++)
            if (ei32[2 * t + 1] != 0) { is64 = 0; break; }
        g_is64 = is64;
    }
}

__global__ void k_count(const void* __restrict__ ei, int E) {
    int e = blockIdx.x * blockDim.x + threadIdx.x;
    if (e < E) {
        int d = load_idx(ei, (size_t)E + e);
        atomicAdd(&g_cnt[d], 1);
    }
}

// unordered CSR row allocation: warp-aggregated atomic on g_alloc + dinv.
__global__ void k_assign(int n) {
    int i = blockIdx.x * blockDim.x + threadIdx.x;
    int lane = threadIdx.x & 31;
    int c = (i < n) ? g_cnt[i] : 0;
    int incl = c;
    #pragma unroll
    for (int off = 1; off < 32; off <<= 1) {
        int t = __shfl_up_sync(0xffffffffu, incl, off);
        if (lane >= off) incl += t;
    }
    int total = __shfl_sync(0xffffffffu, incl, 31);
    int base = 0;
    if (lane == 0) base = atomicAdd(&g_alloc, total);
    base = __shfl_sync(0xffffffffu, base, 0);
    if (i < n) {
        int off = base + incl - c;
        g_rowstart[i] = off;
        g_cursor[i]   = off;
        g_dinv[i]     = rsqrtf((float)(c + 1));  // +1 self-loop
    }
}

__global__ void k_scatter(const void* __restrict__ ei, int E) {
    int e = blockIdx.x * blockDim.x + threadIdx.x;
    if (e < E) {
        int s = load_idx(ei, e);
        int d = load_idx(ei, (size_t)E + e);
        int p = atomicAdd(&g_cursor[d], 1);
        g_ew[p] = make_int2(s, __float_as_int(g_dinv[s]));  // one ST.64
    }
}

// ---------------- GEMM: C[M,128] = A[M,128] @ W[128,128] via tf32 mma.sync ---
// 128x128 block tile, 8 warps, warp tile 32x64. K chunked by 32 with register
// prefetch. Epilogue writes fp32 C and fp16 g_hh.
__device__ __forceinline__ void gemm_impl(const float* __restrict__ A,
                                          const float* __restrict__ W,
                                          float* __restrict__ C, int M) {
    __shared__ float As[128][36];
    __shared__ float Bs[32][136];

    int tid  = threadIdx.x;
    int m0   = blockIdx.x * 128;
    int wid  = tid >> 5, lane = tid & 31;
    int warp_m = wid & 3;
    int warp_n = wid >> 2;
    int gID  = lane >> 2;
    int tig  = lane & 3;

    int am[4], ak4[4], br[4], bc4[4];
    bool aok[4];
    #pragma unroll
    for (int l = 0; l < 4; l++) {
        int idx = l * 256 + tid;
        am[l]  = idx >> 3;  ak4[l] = idx & 7;
        br[l]  = idx >> 5;  bc4[l] = idx & 31;
        aok[l] = (m0 + am[l]) < M;
    }

    const float4* A4 = (const float4*)A;
    const float4* W4 = (const float4*)W;

    float acc[2][8][4];
    #pragma unroll
    for (int mt = 0; mt < 2; mt++)
        #pragma unroll
        for (int nt = 0; nt < 8; nt++)
            #pragma unroll
            for (int r = 0; r < 4; r++) acc[mt][nt][r] = 0.f;

    float4 pa[4], pb[4];
    #pragma unroll
    for (int l = 0; l < 4; l++) {
        pa[l] = aok[l] ? A4[(size_t)(m0 + am[l]) * 32 + ak4[l]]
                       : make_float4(0.f, 0.f, 0.f, 0.f);
        pb[l] = W4[(size_t)br[l] * 32 + bc4[l]];
    }

    #pragma unroll
    for (int kc = 0; kc < 4; kc++) {
        #pragma unroll
        for (int l = 0; l < 4; l++) {
            float4 va = make_float4(f2tf(pa[l].x), f2tf(pa[l].y),
                                    f2tf(pa[l].z), f2tf(pa[l].w));
            *(float4*)&As[am[l]][ak4[l] * 4] = va;
            float4 vb = make_float4(f2tf(pb[l].x), f2tf(pb[l].y),
                                    f2tf(pb[l].z), f2tf(pb[l].w));
            *(float4*)&Bs[br[l]][bc4[l] * 4] = vb;
        }
        if (kc < 3) {
            #pragma unroll
            for (int l = 0; l < 4; l++) {
                pa[l] = aok[l] ? A4[(size_t)(m0 + am[l]) * 32 + (kc + 1) * 8 + ak4[l]]
                               : make_float4(0.f, 0.f, 0.f, 0.f);
                pb[l] = W4[(size_t)((kc + 1) * 32 + br[l]) * 32 + bc4[l]];
            }
        }
        __syncthreads();

        #pragma unroll
        for (int kk = 0; kk < 4; kk++) {
            int cb = kk * 8;
            unsigned a[2][4];
            #pragma unroll
            for (int mt = 0; mt < 2; mt++) {
                int rb = warp_m * 32 + mt * 16;
                a[mt][0] = __float_as_uint(As[rb + gID    ][cb + tig    ]);
                a[mt][1] = __float_as_uint(As[rb + gID + 8][cb + tig    ]);
                a[mt][2] = __float_as_uint(As[rb + gID    ][cb + tig + 4]);
                a[mt][3] = __float_as_uint(As[rb + gID + 8][cb + tig + 4]);
            }
            unsigned b[8][2];
            #pragma unroll
            for (int nt = 0; nt < 8; nt++) {
                int nb = warp_n * 64 + nt * 8;
                b[nt][0] = __float_as_uint(Bs[cb + tig    ][nb + gID]);
                b[nt][1] = __float_as_uint(Bs[cb + tig + 4][nb + gID]);
            }
            #pragma unroll
            for (int mt = 0; mt < 2; mt++)
                #pragma unroll
                for (int nt = 0; nt < 8; nt++)
                    mma_tf32(acc[mt][nt], a[mt], b[nt]);
        }
        __syncthreads();
    }

    // epilogue: fp32 + fp16 copies
    __half2* HH = (__half2*)g_hh;
    #pragma unroll
    for (int mt = 0; mt < 2; mt++) {
        int row0 = m0 + warp_m * 32 + mt * 16 + gID;
        #pragma unroll
        for (int nt = 0; nt < 8; nt++) {
            int col = warp_n * 64 + nt * 8 + tig * 2;
            if (row0 < M) {
                *(float2*)&C[(size_t)row0 * 128 + col] =
                    make_float2(acc[mt][nt][0], acc[mt][nt][1]);
                HH[(size_t)row0 * 64 + (col >> 1)] =
                    __floats2half2_rn(acc[mt][nt][0], acc[mt][nt][1]);
            }
            if (row0 + 8 < M) {
                *(float2*)&C[(size_t)(row0 + 8) * 128 + col] =
                    make_float2(acc[mt][nt][2], acc[mt][nt][3]);
                HH[(size_t)(row0 + 8) * 64 + (col >> 1)] =
                    __floats2half2_rn(acc[mt][nt][2], acc[mt][nt][3]);
            }
        }
    }
}

__global__ void __launch_bounds__(256, 2)
k_gemm1(const float* __restrict__ x, const float* __restrict__ W, int M) {
    gemm_impl(x, W, g_h, M);
}
__global__ void __launch_bounds__(256, 2)
k_gemm2(const float* __restrict__ W, int M) {
    gemm_impl(g_y1, W, g_h, M);
}

// ---------------- aggregation: warp per node, fp16 gather ----------------
// out[d] = relu( dinv[d]*sum_e w_e*h16[src_e] + dinv[d]^2*h32[d] + b )
__device__ __forceinline__ void agg_impl(const float* __restrict__ bias,
                                         float* __restrict__ out, int N) {
    int gwarp = (blockIdx.x * blockDim.x + threadIdx.x) >> 5;
    if (gwarp >= N) return;
    int lane = threadIdx.x & 31;

    int s = g_rowstart[gwarp];
    int e = s + g_cnt[gwarp];

    const uint2* hh = (const uint2*)g_hh;   // row = 32 uint2 (4 halves each)
    float4 acc = make_float4(0.f, 0.f, 0.f, 0.f);

    for (int i = s; i < e; i += 32) {
        int j = i + lane;
        int2 ew = (j < e) ? __ldg(&g_ew[j]) : make_int2(0, 0);
        int nb = min(32, e - i);
        int t = 0;
        for (; t + 4 <= nb; t += 4) {
            int   s0 = __shfl_sync(0xffffffffu, ew.x, t);
            int   s1 = __shfl_sync(0xffffffffu, ew.x, t + 1);
            int   s2 = __shfl_sync(0xffffffffu, ew.x, t + 2);
            int   s3 = __shfl_sync(0xffffffffu, ew.x, t + 3);
            float w0 = __int_as_float(__shfl_sync(0xffffffffu, ew.y, t));
            float w1 = __int_as_float(__shfl_sync(0xffffffffu, ew.y, t + 1));
            float w2 = __int_as_float(__shfl_sync(0xffffffffu, ew.y, t + 2));
            float w3 = __int_as_float(__shfl_sync(0xffffffffu, ew.y, t + 3));
            uint2 r0 = hh[(size_t)s0 * 32 + lane];
            uint2 r1 = hh[(size_t)s1 * 32 + lane];
            uint2 r2 = hh[(size_t)s2 * 32 + lane];
            uint2 r3 = hh[(size_t)s3 * 32 + lane];
            float2 a0 = __half22float2(*(__half2*)&r0.x);
            float2 b0 = __half22float2(*(__half2*)&r0.y);
            float2 a1 = __half22float2(*(__half2*)&r1.x);
            float2 b1 = __half22float2(*(__half2*)&r1.y);
            float2 a2 = __half22float2(*(__half2*)&r2.x);
            float2 b2 = __half22float2(*(__half2*)&r2.y);
            float2 a3 = __half22float2(*(__half2*)&r3.x);
            float2 b3 = __half22float2(*(__half2*)&r3.y);
            acc.x += a0.x * w0; acc.y += a0.y * w0; acc.z += b0.x * w0; acc.w += b0.y * w0;
            acc.x += a1.x * w1; acc.y += a1.y * w1; acc.z += b1.x * w1; acc.w += b1.y * w1;
            acc.x += a2.x * w2; acc.y += a2.y * w2; acc.z += b2.x * w2; acc.w += b2.y * w2;
            acc.x += a3.x * w3; acc.y += a3.y * w3; acc.z += b3.x * w3; acc.w += b3.y * w3;
        }
        for (; t < nb; t++) {
            int   sv = __shfl_sync(0xffffffffu, ew.x, t);
            float ww = __int_as_float(__shfl_sync(0xffffffffu, ew.y, t));
            uint2 r = hh[(size_t)sv * 32 + lane];
            float2 a = __half22float2(*(__half2*)&r.x);
            float2 b = __half22float2(*(__half2*)&r.y);
            acc.x += a.x * ww; acc.y += a.y * ww;
            acc.z += b.x * ww; acc.w += b.y * ww;
        }
    }

    float di  = g_dinv[gwarp];
    float di2 = di * di;
    const float4* h4 = (const float4*)g_h;           // fp32 self term
    float4 sv = h4[(size_t)gwarp * 32 + lane];
    float4 bv = ((const float4*)bias)[lane];

    float4 o;
    o.x = fmaxf(di * acc.x + di2 * sv.x + bv.x, 0.f);
    o.y = fmaxf(di * acc.y + di2 * sv.y + bv.y, 0.f);
    o.z = fmaxf(di * acc.z + di2 * sv.z + bv.z, 0.f);
    o.w = fmaxf(di * acc.w + di2 * sv.w + bv.w, 0.f);
    ((float4*)out)[(size_t)gwarp * 32 + lane] = o;
}

__global__ void k_agg1(const float* __restrict__ bias, int N) {
    agg_impl(bias, g_y1, N);
}
__global__ void k_agg2(const float* __restrict__ bias, float* __restrict__ out, int N) {
    agg_impl(bias, out, N);
}

// ---------------- launch ----------------
extern "C" void kernel_launch(void* const* d_in, const int* in_sizes, int n_in,
                              void* d_out, int out_size) {
    const float* x  = (const float*)d_in[0];
    const void*  ei = d_in[1];
    const float* W1 = (const float*)d_in[2];
    const float* b1 = (const float*)d_in[3];
    const float* W2 = (const float*)d_in[4];
    const float* b2 = (const float*)d_in[5];
    float* out = (float*)d_out;

    int N = in_sizes[0] / FDIM;
    int E = in_sizes[1] / 2;

    // graph build (shared by both layers)
    k_pre    <<<(N + 255) / 256, 256>>>((const int*)ei, N);
    k_count  <<<(E + 255) / 256, 256>>>(ei, E);
    k_assign <<<(N + 255) / 256, 256>>>(N);
    k_scatter<<<(E + 255) / 256, 256>>>(ei, E);

    int gemm_blocks = (N + 127) / 128;
    int agg_blocks  = (int)(((size_t)N * 32 + 255) / 256);

    // layer 1
    k_gemm1<<<gemm_blocks, 256>>>(x, W1, N);
    k_agg1 <<<agg_blocks, 256>>>(b1, N);
    // layer 2
    k_gemm2<<<gemm_blocks, 256>>>(W2, N);
    k_agg2 <<<agg_blocks, 256>>>(b2, out, N);
}